// round 2
// baseline (speedup 1.0000x reference)
#include <cuda_runtime.h>
#include <cuda_bf16.h>
#include <cstdint>
#include <cstddef>

// ============================================================================
// Problem: B=8, M=2048 -> NTOK=16384 tokens, feature dim 1024, H=16, Kd=Vd=64.
// Pipeline: split fp32->bf16(hi,lo); 3 projection GEMMs (tensor cores, 3-pass
// hi/lo for fp32-grade accuracy); per-token attention core in fp32; output GEMM.
// Target is plain sm_100 (no tcgen05!) -> mma.sync + ldmatrix + cp.async.
// ============================================================================
constexpr int NTOK = 16384;
constexpr int FDIM = 1024;
constexpr int NELEM_X = NTOK * FDIM;
constexpr int NELEM_W = FDIM * FDIM;

// ============================================================================
// Scratch (device globals; no allocation allowed)
// ============================================================================
__device__ __nv_bfloat16 g_x1hi[NELEM_X];
__device__ __nv_bfloat16 g_x1lo[NELEM_X];
__device__ __nv_bfloat16 g_x2hi[NELEM_X];
__device__ __nv_bfloat16 g_x2lo[NELEM_X];
__device__ __nv_bfloat16 g_wqhi[NELEM_W];
__device__ __nv_bfloat16 g_wqlo[NELEM_W];
__device__ __nv_bfloat16 g_wkhi[NELEM_W];
__device__ __nv_bfloat16 g_wklo[NELEM_W];
__device__ __nv_bfloat16 g_wvhi[NELEM_W];
__device__ __nv_bfloat16 g_wvlo[NELEM_W];
__device__ __nv_bfloat16 g_wohi[NELEM_W];
__device__ __nv_bfloat16 g_wolo[NELEM_W];
__device__ float g_q1[NELEM_X];
__device__ float g_k2[NELEM_X];
__device__ float g_v2[NELEM_X];
__device__ __nv_bfloat16 g_mhi[NELEM_X];
__device__ __nv_bfloat16 g_mlo[NELEM_X];

#define DINL __device__ __forceinline__

DINL uint32_t smem_u32(const void* p) {
    uint32_t a;
    asm("{ .reg .u64 t; cvta.to.shared.u64 t, %1; cvt.u32.u64 %0, t; }"
        : "=r"(a) : "l"(p));
    return a;
}

#define SW128(o) ((o) ^ (((o) >> 3) & 0x70))

#define CP_ASYNC16(smem_addr, gptr) \
    asm volatile("cp.async.cg.shared.global [%0], [%1], 16;" \
                 :: "r"(smem_addr), "l"(gptr))
#define CP_COMMIT() asm volatile("cp.async.commit_group;")
#define CP_WAIT(n)  asm volatile("cp.async.wait_group %0;" :: "n"(n))

#define LDSM_X4(r0, r1, r2, r3, addr) \
    asm volatile("ldmatrix.sync.aligned.m8n8.x4.shared.b16 {%0,%1,%2,%3}, [%4];" \
                 : "=r"(r0), "=r"(r1), "=r"(r2), "=r"(r3) : "r"(addr))

DINL void mma16816(float* c, const uint32_t* a, const uint32_t* b) {
    asm volatile(
        "mma.sync.aligned.m16n8k16.row.col.f32.bf16.bf16.f32 "
        "{%0,%1,%2,%3}, {%4,%5,%6,%7}, {%8,%9}, {%0,%1,%2,%3};"
        : "+f"(c[0]), "+f"(c[1]), "+f"(c[2]), "+f"(c[3])
        : "r"(a[0]), "r"(a[1]), "r"(a[2]), "r"(a[3]), "r"(b[0]), "r"(b[1]));
}

// ============================================================================
// fp32 -> (bf16 hi, bf16 lo) split
// ============================================================================
__global__ void __launch_bounds__(256) split_kernel(
    const float* __restrict__ in,
    __nv_bfloat16* __restrict__ hi,
    __nv_bfloat16* __restrict__ lo,
    int n4)
{
    int i = blockIdx.x * 256 + threadIdx.x;
    if (i >= n4) return;
    float4 v = reinterpret_cast<const float4*>(in)[i];

    __nv_bfloat16 h0 = __float2bfloat16(v.x);
    __nv_bfloat16 h1 = __float2bfloat16(v.y);
    __nv_bfloat16 h2 = __float2bfloat16(v.z);
    __nv_bfloat16 h3 = __float2bfloat16(v.w);
    __nv_bfloat16 l0 = __float2bfloat16(v.x - __bfloat162float(h0));
    __nv_bfloat16 l1 = __float2bfloat16(v.y - __bfloat162float(h1));
    __nv_bfloat16 l2 = __float2bfloat16(v.z - __bfloat162float(h2));
    __nv_bfloat16 l3 = __float2bfloat16(v.w - __bfloat162float(h3));

    __nv_bfloat162 hp0; hp0.x = h0; hp0.y = h1;
    __nv_bfloat162 hp1; hp1.x = h2; hp1.y = h3;
    __nv_bfloat162 lp0; lp0.x = l0; lp0.y = l1;
    __nv_bfloat162 lp1; lp1.x = l2; lp1.y = l3;
    uint2 uh, ul;
    uh.x = *reinterpret_cast<uint32_t*>(&hp0);
    uh.y = *reinterpret_cast<uint32_t*>(&hp1);
    ul.x = *reinterpret_cast<uint32_t*>(&lp0);
    ul.y = *reinterpret_cast<uint32_t*>(&lp1);
    reinterpret_cast<uint2*>(hi)[i] = uh;
    reinterpret_cast<uint2*>(lo)[i] = ul;
}

// ============================================================================
// Split-bf16 GEMM via mma.sync:  C[m,n] = sum_k A[m,k]*B[n,k]  (+bias)
// 3 passes folded into extended K' = 3*1024: pass0 Ahi*Bhi, pass1 Alo*Bhi,
// pass2 Ahi*Blo, all accumulated in the same fp32 register fragments.
// CTA 128x128, BK=64, 3-stage cp.async pipeline, 8 warps (2x4), warp 64x32.
// ============================================================================
constexpr int BM = 128, BN = 128, BK = 64;
constexpr int STAGES = 3;
constexpr int NT = 3 * (FDIM / BK);           // 48 K'-tiles
constexpr int TILEB = 128 * 128;              // 16 KB per operand tile
constexpr int STAGE_BYTES = 2 * TILEB;        // A + B
constexpr int GEMM_SMEM = STAGES * STAGE_BYTES;   // 96 KB

__global__ void __launch_bounds__(256) gemm_hmma_kernel(
    const __nv_bfloat16* __restrict__ Ahi, const __nv_bfloat16* __restrict__ Alo,
    const __nv_bfloat16* __restrict__ Bhi, const __nv_bfloat16* __restrict__ Blo,
    float* __restrict__ C, const float* __restrict__ bias)
{
    extern __shared__ __align__(1024) char smem[];
    const uint32_t sbase = smem_u32(smem);
    const int tid = threadIdx.x;
    const int wid = tid >> 5;
    const int lid = tid & 31;
    const int wm = wid & 1;          // 0..1 -> m offset wm*64
    const int wn = wid >> 1;         // 0..3 -> n offset wn*32
    const int m0 = blockIdx.y * BM;
    const int n0 = blockIdx.x * BN;

    float acc[4][4][4];
    #pragma unroll
    for (int i = 0; i < 4; ++i)
        #pragma unroll
        for (int j = 0; j < 4; ++j)
            #pragma unroll
            for (int r = 0; r < 4; ++r) acc[i][j][r] = 0.f;

    // ---- stage loader ----
    auto load_stage = [&](int buf, int kt) {
        const int pass = kt >> 4;
        const int k0 = (kt & 15) * BK;
        const __nv_bfloat16* As = (pass == 1) ? Alo : Ahi;
        const __nv_bfloat16* Bs = (pass == 2) ? Blo : Bhi;
        const uint32_t sa = sbase + buf * STAGE_BYTES;
        const uint32_t sb = sa + TILEB;
        #pragma unroll
        for (int i = 0; i < 4; ++i) {
            int chunk = tid + i * 256;          // 0..1023
            int r = chunk >> 3;                  // row 0..127
            int c = chunk & 7;                   // 16B chunk 0..7
            uint32_t sw = SW128((uint32_t)(r * 128 + c * 16));
            CP_ASYNC16(sa + sw, As + (size_t)(m0 + r) * FDIM + k0 + c * 8);
            CP_ASYNC16(sb + sw, Bs + (size_t)(n0 + r) * FDIM + k0 + c * 8);
        }
    };

    // prologue: fill STAGES-1 stages
    load_stage(0, 0); CP_COMMIT();
    load_stage(1, 1); CP_COMMIT();

    for (int kt = 0; kt < NT; ++kt) {
        CP_WAIT(STAGES - 2);       // stage kt arrived
        __syncthreads();           // prior iteration's compute done everywhere

        int nxt = kt + STAGES - 1;
        if (nxt < NT) load_stage(nxt % STAGES, nxt);
        CP_COMMIT();

        const int buf = kt % STAGES;
        const uint32_t sa = sbase + buf * STAGE_BYTES;
        const uint32_t sb = sa + TILEB;

        #pragma unroll
        for (int ks = 0; ks < 4; ++ks) {
            uint32_t af[4][4];
            #pragma unroll
            for (int mt = 0; mt < 4; ++mt) {
                int row = wm * 64 + mt * 16 + ((lid >> 3) & 1) * 8 + (lid & 7);
                int koff = ks * 32 + (lid >> 4) * 16;
                uint32_t ad = sa + SW128((uint32_t)(row * 128 + koff));
                LDSM_X4(af[mt][0], af[mt][1], af[mt][2], af[mt][3], ad);
            }
            uint32_t bf_[4][2];
            #pragma unroll
            for (int bt = 0; bt < 2; ++bt) {
                int row = wn * 32 + bt * 16 + ((lid >> 4) & 1) * 8 + (lid & 7);
                int koff = ks * 32 + ((lid >> 3) & 1) * 16;
                uint32_t bd = sb + SW128((uint32_t)(row * 128 + koff));
                LDSM_X4(bf_[2 * bt][0], bf_[2 * bt][1],
                        bf_[2 * bt + 1][0], bf_[2 * bt + 1][1], bd);
            }
            #pragma unroll
            for (int mt = 0; mt < 4; ++mt)
                #pragma unroll
                for (int nt = 0; nt < 4; ++nt)
                    mma16816(acc[mt][nt], af[mt], bf_[nt]);
        }
    }

    // ---- epilogue ----
    const int g = lid >> 2;
    const int t = lid & 3;
    #pragma unroll
    for (int mt = 0; mt < 4; ++mt) {
        #pragma unroll
        for (int nt = 0; nt < 4; ++nt) {
            int row0 = m0 + wm * 64 + mt * 16 + g;
            int col  = n0 + wn * 32 + nt * 8 + 2 * t;
            float bx = 0.f, by = 0.f;
            if (bias != nullptr) {
                float2 bv = *reinterpret_cast<const float2*>(bias + col);
                bx = bv.x; by = bv.y;
            }
            float2 v0 = make_float2(acc[mt][nt][0] + bx, acc[mt][nt][1] + by);
            float2 v1 = make_float2(acc[mt][nt][2] + bx, acc[mt][nt][3] + by);
            *reinterpret_cast<float2*>(C + (size_t)row0 * FDIM + col) = v0;
            *reinterpret_cast<float2*>(C + (size_t)(row0 + 8) * FDIM + col) = v1;
        }
    }
}

// ============================================================================
// Per-token attention core (fp32):
//   attn[c,d] = softmax_d( (1/8) * sum_h k[h,c] q[h,d] )
//   out[h,d]  = sum_v v[h,v] attn[v,d]
// One CTA per token, 128 threads; outputs bf16 hi/lo for the final GEMM.
// ============================================================================
__global__ void __launch_bounds__(128) middle_kernel(
    const float* __restrict__ q, const float* __restrict__ k,
    const float* __restrict__ v,
    __nv_bfloat16* __restrict__ mhi, __nv_bfloat16* __restrict__ mlo)
{
    __shared__ float sq[1024];
    __shared__ float sk[1024];
    __shared__ float sv[1024];
    __shared__ float sat[64 * 65];

    const int t = blockIdx.x;
    const int tid = threadIdx.x;
    const size_t base = (size_t)t * 1024;

    {
        const float4* qs = reinterpret_cast<const float4*>(q + base);
        const float4* ks = reinterpret_cast<const float4*>(k + base);
        const float4* vs = reinterpret_cast<const float4*>(v + base);
        float4* dq = reinterpret_cast<float4*>(sq);
        float4* dk = reinterpret_cast<float4*>(sk);
        float4* dv = reinterpret_cast<float4*>(sv);
        dq[tid] = qs[tid]; dq[tid + 128] = qs[tid + 128];
        dk[tid] = ks[tid]; dk[tid + 128] = ks[tid + 128];
        dv[tid] = vs[tid]; dv[tid + 128] = vs[tid + 128];
    }
    __syncthreads();

    const int d = tid & 63;
    const int cg = tid >> 6;

    float qreg[16];
    #pragma unroll
    for (int h = 0; h < 16; ++h) qreg[h] = sq[h * 64 + d];
    for (int ci = 0; ci < 32; ++ci) {
        int c = cg * 32 + ci;
        float a = 0.f;
        #pragma unroll
        for (int h = 0; h < 16; ++h) a += sk[h * 64 + c] * qreg[h];
        sat[c * 65 + d] = a * 0.125f;
    }
    __syncthreads();

    if (tid < 64) {
        const int c = tid;
        float m = -1e30f;
        for (int dd = 0; dd < 64; ++dd) m = fmaxf(m, sat[c * 65 + dd]);
        float s = 0.f;
        for (int dd = 0; dd < 64; ++dd) {
            float e = __expf(sat[c * 65 + dd] - m);
            sat[c * 65 + dd] = e;
            s += e;
        }
        float inv = 1.f / s;
        for (int dd = 0; dd < 64; ++dd) sat[c * 65 + dd] *= inv;
    }
    __syncthreads();

    float a8[8];
    #pragma unroll
    for (int j = 0; j < 8; ++j) a8[j] = 0.f;
    for (int vv = 0; vv < 64; ++vv) {
        float a = sat[vv * 65 + d];
        #pragma unroll
        for (int j = 0; j < 8; ++j) a8[j] += sv[(cg * 8 + j) * 64 + vv] * a;
    }
    #pragma unroll
    for (int j = 0; j < 8; ++j) {
        float x = a8[j];
        __nv_bfloat16 h = __float2bfloat16(x);
        __nv_bfloat16 l = __float2bfloat16(x - __bfloat162float(h));
        size_t idx = base + (size_t)(cg * 8 + j) * 64 + d;
        mhi[idx] = h;
        mlo[idx] = l;
    }
}

// ============================================================================
// kernel_launch
// ============================================================================
extern "C" void kernel_launch(void* const* d_in, const int* in_sizes, int n_in,
                              void* d_out, int out_size)
{
    const float* x1 = (const float*)d_in[0];
    const float* x2 = (const float*)d_in[1];
    const float* Wq = (const float*)d_in[2];
    const float* Wk = (const float*)d_in[3];
    const float* Wv = (const float*)d_in[4];
    const float* Wo = (const float*)d_in[5];
    const float* bo = (const float*)d_in[6];
    float* out = (float*)d_out;

    void *px1h, *px1l, *px2h, *px2l;
    void *pwqh, *pwql, *pwkh, *pwkl, *pwvh, *pwvl, *pwoh, *pwol;
    void *pq1, *pk2, *pv2, *pmh, *pml;
    cudaGetSymbolAddress(&px1h, g_x1hi); cudaGetSymbolAddress(&px1l, g_x1lo);
    cudaGetSymbolAddress(&px2h, g_x2hi); cudaGetSymbolAddress(&px2l, g_x2lo);
    cudaGetSymbolAddress(&pwqh, g_wqhi); cudaGetSymbolAddress(&pwql, g_wqlo);
    cudaGetSymbolAddress(&pwkh, g_wkhi); cudaGetSymbolAddress(&pwkl, g_wklo);
    cudaGetSymbolAddress(&pwvh, g_wvhi); cudaGetSymbolAddress(&pwvl, g_wvlo);
    cudaGetSymbolAddress(&pwoh, g_wohi); cudaGetSymbolAddress(&pwol, g_wolo);
    cudaGetSymbolAddress(&pq1, g_q1);   cudaGetSymbolAddress(&pk2, g_k2);
    cudaGetSymbolAddress(&pv2, g_v2);
    cudaGetSymbolAddress(&pmh, g_mhi);  cudaGetSymbolAddress(&pml, g_mlo);

    cudaFuncSetAttribute(gemm_hmma_kernel,
                         cudaFuncAttributeMaxDynamicSharedMemorySize, GEMM_SMEM);

    const int n4x = NELEM_X / 4;
    const int n4w = NELEM_W / 4;

    split_kernel<<<n4x / 256, 256>>>(x1, (__nv_bfloat16*)px1h, (__nv_bfloat16*)px1l, n4x);
    split_kernel<<<n4x / 256, 256>>>(x2, (__nv_bfloat16*)px2h, (__nv_bfloat16*)px2l, n4x);
    split_kernel<<<n4w / 256, 256>>>(Wq, (__nv_bfloat16*)pwqh, (__nv_bfloat16*)pwql, n4w);
    split_kernel<<<n4w / 256, 256>>>(Wk, (__nv_bfloat16*)pwkh, (__nv_bfloat16*)pwkl, n4w);
    split_kernel<<<n4w / 256, 256>>>(Wv, (__nv_bfloat16*)pwvh, (__nv_bfloat16*)pwvl, n4w);
    split_kernel<<<n4w / 256, 256>>>(Wo, (__nv_bfloat16*)pwoh, (__nv_bfloat16*)pwol, n4w);

    dim3 gg(FDIM / BN, NTOK / BM);   // (8, 128)
    gemm_hmma_kernel<<<gg, 256, GEMM_SMEM>>>(
        (const __nv_bfloat16*)px1h, (const __nv_bfloat16*)px1l,
        (const __nv_bfloat16*)pwqh, (const __nv_bfloat16*)pwql,
        (float*)pq1, nullptr);
    gemm_hmma_kernel<<<gg, 256, GEMM_SMEM>>>(
        (const __nv_bfloat16*)px2h, (const __nv_bfloat16*)px2l,
        (const __nv_bfloat16*)pwkh, (const __nv_bfloat16*)pwkl,
        (float*)pk2, nullptr);
    gemm_hmma_kernel<<<gg, 256, GEMM_SMEM>>>(
        (const __nv_bfloat16*)px2h, (const __nv_bfloat16*)px2l,
        (const __nv_bfloat16*)pwvh, (const __nv_bfloat16*)pwvl,
        (float*)pv2, nullptr);

    middle_kernel<<<NTOK, 128>>>(
        (const float*)pq1, (const float*)pk2, (const float*)pv2,
        (__nv_bfloat16*)pmh, (__nv_bfloat16*)pml);

    gemm_hmma_kernel<<<gg, 256, GEMM_SMEM>>>(
        (const __nv_bfloat16*)pmh, (const __nv_bfloat16*)pml,
        (const __nv_bfloat16*)pwoh, (const __nv_bfloat16*)pwol,
        out, bo);
}

// round 4
// speedup vs baseline: 1.0344x; 1.0344x over previous
#include <cuda_runtime.h>
#include <cuda_bf16.h>
#include <cstdint>
#include <cstddef>

// ============================================================================
// Problem: B=8, M=2048 -> NTOK=16384 tokens, feature dim 1024, H=16, Kd=Vd=64.
// split fp32->bf16(hi,lo); 3-pass hi/lo HMMA GEMMs; fp32 attention core; out GEMM.
// Target is plain sm_100 (no tcgen05) -> mma.sync + ldmatrix + cp.async.
// ============================================================================
constexpr int NTOK = 16384;
constexpr int FDIM = 1024;
constexpr int NELEM_X = NTOK * FDIM;
constexpr int NELEM_W = FDIM * FDIM;

__device__ __nv_bfloat16 g_x1hi[NELEM_X];
__device__ __nv_bfloat16 g_x1lo[NELEM_X];
__device__ __nv_bfloat16 g_x2hi[NELEM_X];
__device__ __nv_bfloat16 g_x2lo[NELEM_X];
__device__ __nv_bfloat16 g_wqhi[NELEM_W];
__device__ __nv_bfloat16 g_wqlo[NELEM_W];
__device__ __nv_bfloat16 g_wkhi[NELEM_W];
__device__ __nv_bfloat16 g_wklo[NELEM_W];
__device__ __nv_bfloat16 g_wvhi[NELEM_W];
__device__ __nv_bfloat16 g_wvlo[NELEM_W];
__device__ __nv_bfloat16 g_wohi[NELEM_W];
__device__ __nv_bfloat16 g_wolo[NELEM_W];
__device__ float g_q1[NELEM_X];
__device__ float g_k2[NELEM_X];
__device__ float g_v2[NELEM_X];
__device__ __nv_bfloat16 g_mhi[NELEM_X];
__device__ __nv_bfloat16 g_mlo[NELEM_X];

#define DINL __device__ __forceinline__

DINL uint32_t smem_u32(const void* p) {
    uint32_t a;
    asm("{ .reg .u64 t; cvta.to.shared.u64 t, %1; cvt.u32.u64 %0, t; }"
        : "=r"(a) : "l"(p));
    return a;
}

#define SW128(o) ((o) ^ (((o) >> 3) & 0x70))

#define CP_ASYNC16(smem_addr, gptr) \
    asm volatile("cp.async.cg.shared.global [%0], [%1], 16;" \
                 :: "r"(smem_addr), "l"(gptr))
#define CP_COMMIT() asm volatile("cp.async.commit_group;")
#define CP_WAIT(n)  asm volatile("cp.async.wait_group %0;" :: "n"(n))

#define LDSM_X4(r0, r1, r2, r3, addr) \
    asm volatile("ldmatrix.sync.aligned.m8n8.x4.shared.b16 {%0,%1,%2,%3}, [%4];" \
                 : "=r"(r0), "=r"(r1), "=r"(r2), "=r"(r3) : "r"(addr))

DINL void mma16816(float* c, const uint32_t* a, const uint32_t* b) {
    asm volatile(
        "mma.sync.aligned.m16n8k16.row.col.f32.bf16.bf16.f32 "
        "{%0,%1,%2,%3}, {%4,%5,%6,%7}, {%8,%9}, {%0,%1,%2,%3};"
        : "+f"(c[0]), "+f"(c[1]), "+f"(c[2]), "+f"(c[3])
        : "r"(a[0]), "r"(a[1]), "r"(a[2]), "r"(a[3]), "r"(b[0]), "r"(b[1]));
}

// ============================================================================
// fp32 -> (bf16 hi, bf16 lo) split
// ============================================================================
__global__ void __launch_bounds__(256) split_kernel(
    const float* __restrict__ in,
    __nv_bfloat16* __restrict__ hi,
    __nv_bfloat16* __restrict__ lo,
    int n4)
{
    int i = blockIdx.x * 256 + threadIdx.x;
    if (i >= n4) return;
    float4 v = reinterpret_cast<const float4*>(in)[i];

    __nv_bfloat16 h0 = __float2bfloat16(v.x);
    __nv_bfloat16 h1 = __float2bfloat16(v.y);
    __nv_bfloat16 h2 = __float2bfloat16(v.z);
    __nv_bfloat16 h3 = __float2bfloat16(v.w);
    __nv_bfloat16 l0 = __float2bfloat16(v.x - __bfloat162float(h0));
    __nv_bfloat16 l1 = __float2bfloat16(v.y - __bfloat162float(h1));
    __nv_bfloat16 l2 = __float2bfloat16(v.z - __bfloat162float(h2));
    __nv_bfloat16 l3 = __float2bfloat16(v.w - __bfloat162float(h3));

    __nv_bfloat162 hp0; hp0.x = h0; hp0.y = h1;
    __nv_bfloat162 hp1; hp1.x = h2; hp1.y = h3;
    __nv_bfloat162 lp0; lp0.x = l0; lp0.y = l1;
    __nv_bfloat162 lp1; lp1.x = l2; lp1.y = l3;
    uint2 uh, ul;
    uh.x = *reinterpret_cast<uint32_t*>(&hp0);
    uh.y = *reinterpret_cast<uint32_t*>(&hp1);
    ul.x = *reinterpret_cast<uint32_t*>(&lp0);
    ul.y = *reinterpret_cast<uint32_t*>(&lp1);
    reinterpret_cast<uint2*>(hi)[i] = uh;
    reinterpret_cast<uint2*>(lo)[i] = ul;
}

// ============================================================================
// Split-bf16 GEMM via mma.sync: C[m,n] = sum_k A[m,k]*B[n,k] (+bias)
// 3 passes folded into K' = 3*1024 (Ahi*Bhi, Alo*Bhi, Ahi*Blo), same fp32 accs.
// CTA 128x128, BK=64, 3-stage cp.async pipeline (96 KB smem, proven config),
// register-double-buffered ldmatrix fragments, 8 warps (2x4), warp tile 64x32.
// ============================================================================
constexpr int BM = 128, BN = 128, BK = 64;
constexpr int STAGES = 3;
constexpr int NT = 3 * (FDIM / BK);           // 48
constexpr int TILEB = 128 * 128;              // 16 KB
constexpr int STAGE_BYTES = 2 * TILEB;
constexpr int GEMM_SMEM = STAGES * STAGE_BYTES;   // 96 KB

__global__ void __launch_bounds__(256) gemm_hmma_kernel(
    const __nv_bfloat16* __restrict__ Ahi, const __nv_bfloat16* __restrict__ Alo,
    const __nv_bfloat16* __restrict__ Bhi, const __nv_bfloat16* __restrict__ Blo,
    float* __restrict__ C, const float* __restrict__ bias)
{
    extern __shared__ __align__(1024) char smem[];
    const uint32_t sbase = smem_u32(smem);
    const int tid = threadIdx.x;
    const int wid = tid >> 5;
    const int lid = tid & 31;
    const int wm = wid & 1;
    const int wn = wid >> 1;
    const int m0 = blockIdx.y * BM;
    const int n0 = blockIdx.x * BN;

    float acc[4][4][4];
    #pragma unroll
    for (int i = 0; i < 4; ++i)
        #pragma unroll
        for (int j = 0; j < 4; ++j)
            #pragma unroll
            for (int r = 0; r < 4; ++r) acc[i][j][r] = 0.f;

    // per-lane ldmatrix address components (buffer/kstep-invariant parts)
    const int arow_base = wm * 64 + ((lid >> 3) & 1) * 8 + (lid & 7);
    const int akoff     = (lid >> 4) * 16;
    const int brow_base = wn * 32 + ((lid >> 4) & 1) * 8 + (lid & 7);
    const int bkoff     = ((lid >> 3) & 1) * 16;

    auto load_stage = [&](int buf, int kt) {
        const int pass = kt >> 4;
        const int k0 = (kt & 15) * BK;
        const __nv_bfloat16* As = (pass == 1) ? Alo : Ahi;
        const __nv_bfloat16* Bs = (pass == 2) ? Blo : Bhi;
        const uint32_t sa = sbase + buf * STAGE_BYTES;
        const uint32_t sb = sa + TILEB;
        #pragma unroll
        for (int i = 0; i < 4; ++i) {
            int chunk = tid + i * 256;
            int r = chunk >> 3;
            int c = chunk & 7;
            uint32_t sw = SW128((uint32_t)(r * 128 + c * 16));
            CP_ASYNC16(sa + sw, As + (size_t)(m0 + r) * FDIM + k0 + c * 8);
            CP_ASYNC16(sb + sw, Bs + (size_t)(n0 + r) * FDIM + k0 + c * 8);
        }
    };

    auto load_frags = [&](uint32_t sa, uint32_t sb, int ks,
                          uint32_t (*af)[4], uint32_t (*bf_)[2]) {
        #pragma unroll
        for (int mt = 0; mt < 4; ++mt) {
            uint32_t ad = sa + SW128((uint32_t)((arow_base + mt * 16) * 128 +
                                                ks * 32 + akoff));
            LDSM_X4(af[mt][0], af[mt][1], af[mt][2], af[mt][3], ad);
        }
        #pragma unroll
        for (int bt = 0; bt < 2; ++bt) {
            uint32_t bd = sb + SW128((uint32_t)((brow_base + bt * 16) * 128 +
                                                ks * 32 + bkoff));
            LDSM_X4(bf_[2 * bt][0], bf_[2 * bt][1],
                    bf_[2 * bt + 1][0], bf_[2 * bt + 1][1], bd);
        }
    };

    // prologue: fill STAGES-1 stages
    load_stage(0, 0); CP_COMMIT();
    load_stage(1, 1); CP_COMMIT();

    uint32_t af[2][4][4];
    uint32_t bf_[2][4][2];

    for (int kt = 0; kt < NT; ++kt) {
        CP_WAIT(STAGES - 2);
        __syncthreads();

        int nxt = kt + STAGES - 1;
        if (nxt < NT) load_stage(nxt % STAGES, nxt);
        CP_COMMIT();

        const int buf = kt % STAGES;
        const uint32_t sa = sbase + buf * STAGE_BYTES;
        const uint32_t sb = sa + TILEB;

        load_frags(sa, sb, 0, af[0], bf_[0]);
        #pragma unroll
        for (int ks = 0; ks < 4; ++ks) {
            const int cur = ks & 1;
            if (ks < 3) load_frags(sa, sb, ks + 1, af[cur ^ 1], bf_[cur ^ 1]);
            #pragma unroll
            for (int mt = 0; mt < 4; ++mt)
                #pragma unroll
                for (int nt = 0; nt < 4; ++nt)
                    mma16816(acc[mt][nt], af[cur][mt], bf_[cur][nt]);
        }
    }

    // epilogue
    const int g = lid >> 2;
    const int t = lid & 3;
    #pragma unroll
    for (int mt = 0; mt < 4; ++mt) {
        #pragma unroll
        for (int nt = 0; nt < 4; ++nt) {
            int row0 = m0 + wm * 64 + mt * 16 + g;
            int col  = n0 + wn * 32 + nt * 8 + 2 * t;
            float bx = 0.f, by = 0.f;
            if (bias != nullptr) {
                float2 bv = *reinterpret_cast<const float2*>(bias + col);
                bx = bv.x; by = bv.y;
            }
            float2 v0 = make_float2(acc[mt][nt][0] + bx, acc[mt][nt][1] + by);
            float2 v1 = make_float2(acc[mt][nt][2] + bx, acc[mt][nt][3] + by);
            *reinterpret_cast<float2*>(C + (size_t)row0 * FDIM + col) = v0;
            *reinterpret_cast<float2*>(C + (size_t)(row0 + 8) * FDIM + col) = v1;
        }
    }
}

// ============================================================================
// Per-token attention core (fp32), float4-vectorized smem traffic:
//   attn[c,d] = softmax_d( (1/8) * sum_h k[h,c] q[h,d] )
//   out[h,d]  = sum_v v[h,v] attn[v,d]
// One CTA per token, 128 threads; outputs bf16 hi/lo for the final GEMM.
// ============================================================================
__global__ void __launch_bounds__(128) middle_kernel(
    const float* __restrict__ q, const float* __restrict__ k,
    const float* __restrict__ v,
    __nv_bfloat16* __restrict__ mhi, __nv_bfloat16* __restrict__ mlo)
{
    __shared__ float sq[1024];
    __shared__ float sk[1024];
    __shared__ float sv[1024];
    __shared__ float sat[64 * 65];

    const int t = blockIdx.x;
    const int tid = threadIdx.x;
    const size_t base = (size_t)t * 1024;

    {
        const float4* qs = reinterpret_cast<const float4*>(q + base);
        const float4* ks = reinterpret_cast<const float4*>(k + base);
        const float4* vs = reinterpret_cast<const float4*>(v + base);
        float4* dq = reinterpret_cast<float4*>(sq);
        float4* dk = reinterpret_cast<float4*>(sk);
        float4* dv = reinterpret_cast<float4*>(sv);
        dq[tid] = qs[tid]; dq[tid + 128] = qs[tid + 128];
        dk[tid] = ks[tid]; dk[tid + 128] = ks[tid + 128];
        dv[tid] = vs[tid]; dv[tid + 128] = vs[tid + 128];
    }
    __syncthreads();

    const int d = tid & 63;
    const int cg = tid >> 6;

    float qreg[16];
    #pragma unroll
    for (int h = 0; h < 16; ++h) qreg[h] = sq[h * 64 + d];

    // phase A: logits, 4 c's per block; sk loads are broadcast float4
    #pragma unroll
    for (int cb = 0; cb < 8; ++cb) {
        const int c0 = cg * 32 + cb * 4;
        float4 a4 = make_float4(0.f, 0.f, 0.f, 0.f);
        #pragma unroll
        for (int h = 0; h < 16; ++h) {
            float4 k4 = *reinterpret_cast<const float4*>(&sk[h * 64 + c0]);
            float qh = qreg[h];
            a4.x += k4.x * qh; a4.y += k4.y * qh;
            a4.z += k4.z * qh; a4.w += k4.w * qh;
        }
        sat[(c0 + 0) * 65 + d] = a4.x * 0.125f;
        sat[(c0 + 1) * 65 + d] = a4.y * 0.125f;
        sat[(c0 + 2) * 65 + d] = a4.z * 0.125f;
        sat[(c0 + 3) * 65 + d] = a4.w * 0.125f;
    }
    __syncthreads();

    // softmax over d for each row c
    if (tid < 64) {
        const int c = tid;
        float m = -1e30f;
        for (int dd = 0; dd < 64; ++dd) m = fmaxf(m, sat[c * 65 + dd]);
        float s = 0.f;
        for (int dd = 0; dd < 64; ++dd) {
            float e = __expf(sat[c * 65 + dd] - m);
            sat[c * 65 + dd] = e;
            s += e;
        }
        float inv = 1.f / s;
        for (int dd = 0; dd < 64; ++dd) sat[c * 65 + dd] *= inv;
    }
    __syncthreads();

    // phase C: out[h,d]; sv loads are broadcast float4 (4 v's at once)
    float a8[8];
    #pragma unroll
    for (int j = 0; j < 8; ++j) a8[j] = 0.f;
    #pragma unroll 4
    for (int vb = 0; vb < 16; ++vb) {
        const int v0 = vb * 4;
        float s0 = sat[(v0 + 0) * 65 + d];
        float s1 = sat[(v0 + 1) * 65 + d];
        float s2 = sat[(v0 + 2) * 65 + d];
        float s3 = sat[(v0 + 3) * 65 + d];
        #pragma unroll
        for (int j = 0; j < 8; ++j) {
            float4 v4 = *reinterpret_cast<const float4*>(&sv[(cg * 8 + j) * 64 + v0]);
            a8[j] += v4.x * s0 + v4.y * s1 + v4.z * s2 + v4.w * s3;
        }
    }
    #pragma unroll
    for (int j = 0; j < 8; ++j) {
        float x = a8[j];
        __nv_bfloat16 h = __float2bfloat16(x);
        __nv_bfloat16 l = __float2bfloat16(x - __bfloat162float(h));
        size_t idx = base + (size_t)(cg * 8 + j) * 64 + d;
        mhi[idx] = h;
        mlo[idx] = l;
    }
}

// ============================================================================
// kernel_launch  (order chosen so ncu -s 5 captures the first GEMM)
// ============================================================================
extern "C" void kernel_launch(void* const* d_in, const int* in_sizes, int n_in,
                              void* d_out, int out_size)
{
    const float* x1 = (const float*)d_in[0];
    const float* x2 = (const float*)d_in[1];
    const float* Wq = (const float*)d_in[2];
    const float* Wk = (const float*)d_in[3];
    const float* Wv = (const float*)d_in[4];
    const float* Wo = (const float*)d_in[5];
    const float* bo = (const float*)d_in[6];
    float* out = (float*)d_out;

    void *px1h, *px1l, *px2h, *px2l;
    void *pwqh, *pwql, *pwkh, *pwkl, *pwvh, *pwvl, *pwoh, *pwol;
    void *pq1, *pk2, *pv2, *pmh, *pml;
    cudaGetSymbolAddress(&px1h, g_x1hi); cudaGetSymbolAddress(&px1l, g_x1lo);
    cudaGetSymbolAddress(&px2h, g_x2hi); cudaGetSymbolAddress(&px2l, g_x2lo);
    cudaGetSymbolAddress(&pwqh, g_wqhi); cudaGetSymbolAddress(&pwql, g_wqlo);
    cudaGetSymbolAddress(&pwkh, g_wkhi); cudaGetSymbolAddress(&pwkl, g_wklo);
    cudaGetSymbolAddress(&pwvh, g_wvhi); cudaGetSymbolAddress(&pwvl, g_wvlo);
    cudaGetSymbolAddress(&pwoh, g_wohi); cudaGetSymbolAddress(&pwol, g_wolo);
    cudaGetSymbolAddress(&pq1, g_q1);   cudaGetSymbolAddress(&pk2, g_k2);
    cudaGetSymbolAddress(&pv2, g_v2);
    cudaGetSymbolAddress(&pmh, g_mhi);  cudaGetSymbolAddress(&pml, g_mlo);

    cudaFuncSetAttribute(gemm_hmma_kernel,
                         cudaFuncAttributeMaxDynamicSharedMemorySize, GEMM_SMEM);

    const int n4x = NELEM_X / 4;
    const int n4w = NELEM_W / 4;

    // launches 0..4: splits needed by the projection GEMMs
    split_kernel<<<n4x / 256, 256>>>(x1, (__nv_bfloat16*)px1h, (__nv_bfloat16*)px1l, n4x);
    split_kernel<<<n4x / 256, 256>>>(x2, (__nv_bfloat16*)px2h, (__nv_bfloat16*)px2l, n4x);
    split_kernel<<<n4w / 256, 256>>>(Wq, (__nv_bfloat16*)pwqh, (__nv_bfloat16*)pwql, n4w);
    split_kernel<<<n4w / 256, 256>>>(Wk, (__nv_bfloat16*)pwkh, (__nv_bfloat16*)pwkl, n4w);
    split_kernel<<<n4w / 256, 256>>>(Wv, (__nv_bfloat16*)pwvh, (__nv_bfloat16*)pwvl, n4w);

    dim3 gg(FDIM / BN, NTOK / BM);   // (8, 128)
    // launch 5: Q GEMM (ncu -s 5 -c 1 captures this)
    gemm_hmma_kernel<<<gg, 256, GEMM_SMEM>>>(
        (const __nv_bfloat16*)px1h, (const __nv_bfloat16*)px1l,
        (const __nv_bfloat16*)pwqh, (const __nv_bfloat16*)pwql,
        (float*)pq1, nullptr);
    gemm_hmma_kernel<<<gg, 256, GEMM_SMEM>>>(
        (const __nv_bfloat16*)px2h, (const __nv_bfloat16*)px2l,
        (const __nv_bfloat16*)pwkh, (const __nv_bfloat16*)pwkl,
        (float*)pk2, nullptr);
    gemm_hmma_kernel<<<gg, 256, GEMM_SMEM>>>(
        (const __nv_bfloat16*)px2h, (const __nv_bfloat16*)px2l,
        (const __nv_bfloat16*)pwvh, (const __nv_bfloat16*)pwvl,
        (float*)pv2, nullptr);

    split_kernel<<<n4w / 256, 256>>>(Wo, (__nv_bfloat16*)pwoh, (__nv_bfloat16*)pwol, n4w);

    middle_kernel<<<NTOK, 128>>>(
        (const float*)pq1, (const float*)pk2, (const float*)pv2,
        (__nv_bfloat16*)pmh, (__nv_bfloat16*)pml);

    gemm_hmma_kernel<<<gg, 256, GEMM_SMEM>>>(
        (const __nv_bfloat16*)pmh, (const __nv_bfloat16*)pml,
        (const __nv_bfloat16*)pwoh, (const __nv_bfloat16*)pwol,
        out, bo);
}